// round 14
// baseline (speedup 1.0000x reference)
#include <cuda_runtime.h>
#include <cuda_fp16.h>
#include <math.h>
#include <stdint.h>

#define N_TOKENS 16384
#define HIDDEN   4096
#define NEXP     64
#define TOPK     8

#define BM       128          // tokens per CTA
#define TK       64           // k per stage
#define NT       (HIDDEN/TK)  // 64 stages
#define NTH      512          // 16 warps: 2 k-groups x (4M x 2N), warp tile 32x32
#define NSTG     4            // smem ring depth

// per-stage smem layout (bytes)
#define A_TERM   16384        // 128 rows x 64 k x 2B
#define A_STG    32768        // 2 fp16 terms
#define B_TERM   8192         // 64 rows x 64 k x 2B
#define B_STG    16384
#define STAGE_BYTES (A_STG + B_STG)        // 49152
#define SMEM_BYTES  (1024 + NSTG*STAGE_BYTES)  // 197632
#define CRS      72           // epilogue C row stride (floats)

#define SCALE_IN   2048.0f            // 2^11 on both x and W
#define SCALE_OUT  (1.0f/4194304.0f)  // exact 2^-22

// pre-split, pre-swizzled W (x2048, 2 fp16 terms): [stage][term][e][64k] (1 MB)
__device__ __align__(16) unsigned char g_wb[NT * B_STG];

// ---------------- helpers ----------------
__device__ __forceinline__ uint32_t smem_u32(const void* p) {
    uint32_t a;
    asm("{ .reg .u64 t; cvta.to.shared.u64 t, %1; cvt.u32.u64 %0, t; }" : "=r"(a) : "l"(p));
    return a;
}
__device__ __forceinline__ uint32_t sw128(uint32_t o) { return o ^ ((o >> 3) & 0x70); }

// pack two f32 into f16x2: lo = first arg, hi = second (first PTX src = high)
#define PACK_F16X2(res, lo, hi) \
    asm("cvt.rn.f16x2.f32 %0, %1, %2;" : "=r"(res) : "f"(hi), "f"(lo))

__device__ __forceinline__ void sts64(uint32_t a, uint32_t x, uint32_t y) {
    asm volatile("st.shared.v2.b32 [%0], {%1,%2};" :: "r"(a), "r"(x), "r"(y) : "memory");
}
__device__ __forceinline__ void cp_async16(uint32_t dst, const void* src) {
    asm volatile("cp.async.cg.shared.global [%0], [%1], 16;" :: "r"(dst), "l"(src) : "memory");
}
#define CP_COMMIT() asm volatile("cp.async.commit_group;" ::: "memory")
#define CP_WAIT0()  asm volatile("cp.async.wait_group 0;" ::: "memory")
#define CP_WAIT2()  asm volatile("cp.async.wait_group 2;" ::: "memory")

__device__ __forceinline__ void ldsm_x4(uint32_t r[4], uint32_t addr) {
    asm volatile("ldmatrix.sync.aligned.m8n8.x4.shared.b16 {%0,%1,%2,%3}, [%4];"
        : "=r"(r[0]), "=r"(r[1]), "=r"(r[2]), "=r"(r[3]) : "r"(addr));
}
__device__ __forceinline__ void mma16816(float c[4], const uint32_t a[4],
                                         uint32_t b0, uint32_t b1) {
    asm volatile("mma.sync.aligned.m16n8k16.row.col.f32.f16.f16.f32 "
        "{%0,%1,%2,%3}, {%4,%5,%6,%7}, {%8,%9}, {%0,%1,%2,%3};"
        : "+f"(c[0]), "+f"(c[1]), "+f"(c[2]), "+f"(c[3])
        : "r"(a[0]), "r"(a[1]), "r"(a[2]), "r"(a[3]), "r"(b0), "r"(b1));
}

// x*2^11 = h0 + h1 (+ eps ~2^-22 rel). h0 roundtrip exact; r exact (Sterbenz).
__device__ __forceinline__ void splitf16(float v, float& f0, float& r) {
    f0 = __half2float(__float2half_rn(v));
    r  = v - f0;
}

// ---------------- W pre-split kernel ----------------
__global__ void wsplit_kernel(const float* __restrict__ W) {
    const int t = blockIdx.x;                 // stage (64 k)
    unsigned char* dst = g_wb + (size_t)t * B_STG;
    for (int item = threadIdx.x; item < NEXP * 16; item += blockDim.x) {
        const int e = item >> 4;              // expert row
        const int k = (item & 15) * 4;        // k within stage
        float4 w = *(const float4*)(W + (size_t)e * HIDDEN + t * TK + k);
        float v[4] = {w.x * SCALE_IN, w.y * SCALE_IN, w.z * SCALE_IN, w.w * SCALE_IN};
        float f0[4], r[4];
#pragma unroll
        for (int i = 0; i < 4; i++) splitf16(v[i], f0[i], r[i]);
        uint32_t u0a, u0b, u1a, u1b;
        PACK_F16X2(u0a, f0[0], f0[1]); PACK_F16X2(u0b, f0[2], f0[3]);
        PACK_F16X2(u1a, r[0],  r[1]);  PACK_F16X2(u1b, r[2],  r[3]);
        const uint32_t off = sw128((uint32_t)(e * 128 + k * 2));
        *(uint2*)(dst + 0 * B_TERM + off) = make_uint2(u0a, u0b);
        *(uint2*)(dst + 1 * B_TERM + off) = make_uint2(u1a, u1b);
    }
}

// MMA over one 64-k stage, warp tile 32x32, merged accumulator.
// products h0w0, h0w1, h1w0 all -> acc (drained per stage).
__device__ __forceinline__ void mma_stage(
    uint32_t Ab, float acc[2][4][4],
    uint32_t arow0, uint32_t arow1, uint32_t brow0, uint32_t brow1,
    uint32_t colb, uint32_t swz)
{
    const uint32_t Bb = Ab + A_STG;
#pragma unroll
    for (int k16 = 0; k16 < 4; k16++) {
        const uint32_t coff = (colb + 32u * k16) ^ swz;

        uint32_t B00[4], B01[4], B10[4], B11[4];
        ldsm_x4(B00, Bb + 0 * B_TERM + brow0 + coff);   // w0, n16-0
        ldsm_x4(B01, Bb + 0 * B_TERM + brow1 + coff);   // w0, n16-1
        ldsm_x4(B10, Bb + 1 * B_TERM + brow0 + coff);   // w1, n16-0
        ldsm_x4(B11, Bb + 1 * B_TERM + brow1 + coff);   // w1, n16-1

        uint32_t A00[4], A01[4], A10[4], A11[4];
        ldsm_x4(A00, Ab + 0 * A_TERM + arow0 + coff);   // h0, m16-0
        ldsm_x4(A01, Ab + 0 * A_TERM + arow1 + coff);   // h0, m16-1
        ldsm_x4(A10, Ab + 1 * A_TERM + arow0 + coff);   // h1, m16-0
        ldsm_x4(A11, Ab + 1 * A_TERM + arow1 + coff);   // h1, m16-1

#pragma unroll
        for (int im = 0; im < 2; im++) {
            const uint32_t* Ah0 = (im == 0) ? A00 : A01;
            const uint32_t* Ah1 = (im == 0) ? A10 : A11;
            // h0*w0
            mma16816(acc[im][0], Ah0, B00[0], B00[2]);
            mma16816(acc[im][1], Ah0, B00[1], B00[3]);
            mma16816(acc[im][2], Ah0, B01[0], B01[2]);
            mma16816(acc[im][3], Ah0, B01[1], B01[3]);
            // h0*w1
            mma16816(acc[im][0], Ah0, B10[0], B10[2]);
            mma16816(acc[im][1], Ah0, B10[1], B10[3]);
            mma16816(acc[im][2], Ah0, B11[0], B11[2]);
            mma16816(acc[im][3], Ah0, B11[1], B11[3]);
            // h1*w0
            mma16816(acc[im][0], Ah1, B00[0], B00[2]);
            mma16816(acc[im][1], Ah1, B00[1], B00[3]);
            mma16816(acc[im][2], Ah1, B01[0], B01[2]);
            mma16816(acc[im][3], Ah1, B01[1], B01[3]);
        }
    }
}

#define DRAIN()                                                \
    do {                                                       \
        _Pragma("unroll")                                      \
        for (int _i = 0; _i < 2; _i++)                         \
        _Pragma("unroll")                                      \
        for (int _j = 0; _j < 4; _j++)                         \
        _Pragma("unroll")                                      \
        for (int _q = 0; _q < 4; _q++) {                       \
            sum[_i][_j][_q] += acc[_i][_j][_q];                \
            acc[_i][_j][_q] = 0.0f;                            \
        }                                                      \
    } while (0)

// ---------------- main kernel ----------------
__global__ __launch_bounds__(NTH, 1) void router_kernel(
    const float* __restrict__ x,
    const float* __restrict__ b,
    float* __restrict__ out)
{
    extern __shared__ __align__(16) char dsmem[];
    float* biasS = (float*)dsmem;                 // [64]
    const uint32_t TBu = smem_u32(dsmem + 1024);
    // epilogue C in stage-0 region (final MMAs read stages 2 and 3)
    float* Cs = (float*)(dsmem + 1024);

    const int tid = threadIdx.x;
    const int wid = tid >> 5;
    const int lid = tid & 31;
    const int block_m = blockIdx.x * BM;

    // k-groups: group g MMAs tiles with tile%2==g. 8 warps per group,
    // warp grid 4 (M) x 2 (N), warp tile 32x32.
    const int group = wid >> 3;
    const int w8 = wid & 7;
    const int wm = (w8 & 3) * 32;
    const int wn = (w8 >> 2) * 32;

    // ldmatrix lane addressing
    const uint32_t lrow = (lid & 7) + ((lid >> 3) & 1) * 8;  // 0..15
    const uint32_t swz  = (lrow & 7) << 4;
    const uint32_t colb = (lid >> 4) * 16;
    const uint32_t arow0 = (wm + lrow) * 128;
    const uint32_t arow1 = arow0 + 16 * 128;
    const uint32_t brow0 = (wn + lrow) * 128;
    const uint32_t brow1 = brow0 + 16 * 128;

    // A conversion mapping: 16 contiguous k per thread, one row
    const int r  = tid >> 2;          // token row 0..127
    const int kq = (tid & 3) * 16;    // k base within stage
    const float* xrow = x + (size_t)(block_m + r) * HIDDEN + kq;
    const uint32_t aoffs[4] = {
        sw128((uint32_t)(r * 128 + kq * 2)),
        sw128((uint32_t)(r * 128 + kq * 2 + 8)),
        sw128((uint32_t)(r * 128 + kq * 2 + 16)),
        sw128((uint32_t)(r * 128 + kq * 2 + 24))};

    float acc[2][4][4], sum[2][4][4];
#pragma unroll
    for (int i = 0; i < 2; i++)
#pragma unroll
        for (int j = 0; j < 4; j++)
#pragma unroll
            for (int q = 0; q < 4; q++) { acc[i][j][q] = 0.0f; sum[i][j][q] = 0.0f; }

    const uint32_t stg[NSTG] = {TBu, TBu + STAGE_BYTES,
                                TBu + 2 * STAGE_BYTES, TBu + 3 * STAGE_BYTES};

    float4 ax[4];

#define CONVERT_A(Abase)                                                       \
    do {                                                                       \
        _Pragma("unroll")                                                      \
        for (int j = 0; j < 4; j++) {                                          \
            float v[4] = {ax[j].x * SCALE_IN, ax[j].y * SCALE_IN,              \
                          ax[j].z * SCALE_IN, ax[j].w * SCALE_IN};             \
            float f0[4], rr[4];                                                \
            _Pragma("unroll")                                                  \
            for (int i = 0; i < 4; i++) splitf16(v[i], f0[i], rr[i]);          \
            uint32_t u0a, u0b, u1a, u1b;                                       \
            PACK_F16X2(u0a, f0[0], f0[1]); PACK_F16X2(u0b, f0[2], f0[3]);      \
            PACK_F16X2(u1a, rr[0], rr[1]); PACK_F16X2(u1b, rr[2], rr[3]);      \
            sts64((Abase) + 0 * A_TERM + aoffs[j], u0a, u0b);                  \
            sts64((Abase) + 1 * A_TERM + aoffs[j], u1a, u1b);                  \
        }                                                                      \
    } while (0)

#define CP_B(stage_base, tile)                                                 \
    do {                                                                       \
        const unsigned char* _src = g_wb + (size_t)(tile) * B_STG;             \
        _Pragma("unroll")                                                      \
        for (int _j = 0; _j < 2; _j++) {                                       \
            const int _idx = tid + _j * NTH;                                   \
            cp_async16((stage_base) + A_STG + _idx * 16,                       \
                       _src + (size_t)_idx * 16);                              \
        }                                                                      \
        CP_COMMIT();                                                           \
    } while (0)

    // ---- prologue: B0..B2 via cp.async; convert tiles 0..2; prefetch ax(3)
    CP_B(stg[0], 0);
    CP_B(stg[1], 1);
    CP_B(stg[2], 2);

#pragma unroll
    for (int j = 0; j < 4; j++) ax[j] = *(const float4*)(xrow + j * 4);
    CONVERT_A(stg[0]);
#pragma unroll
    for (int j = 0; j < 4; j++) ax[j] = *(const float4*)(xrow + TK + j * 4);
    CONVERT_A(stg[1]);
#pragma unroll
    for (int j = 0; j < 4; j++) ax[j] = *(const float4*)(xrow + 2 * TK + j * 4);
    CONVERT_A(stg[2]);
#pragma unroll
    for (int j = 0; j < 4; j++) ax[j] = *(const float4*)(xrow + 3 * TK + j * 4);

    if (tid < NEXP) biasS[tid] = b[tid];

    CP_WAIT2();              // B0 landed
    __syncthreads();

    // ---- main loop: period t: group ((t-1)&1) MMAs tile t-1; all build t+2
    int srd = 0;             // stage of tile t-1
    int swr = 3;             // stage of tile t+2
    for (int t = 1; t < NT; ++t) {
        if (((t - 1) & 1) == group) {
            mma_stage(stg[srd], acc, arow0, arow1, brow0, brow1, colb, swz);
            DRAIN();
        }

        if (t + 2 < NT) {
            CONVERT_A(stg[swr]);
            CP_B(stg[swr], t + 2);
            if (t + 3 < NT) {
                const float* xn = xrow + (size_t)(t + 3) * TK;
#pragma unroll
                for (int j = 0; j < 4; j++) ax[j] = *(const float4*)(xn + j * 4);
            }
            CP_WAIT2();      // B(t) complete (two newer groups may be in flight)
        } else {
            CP_WAIT0();      // all B complete
        }
        __syncthreads();

        srd = (srd == NSTG - 1) ? 0 : srd + 1;
        swr = (swr == NSTG - 1) ? 0 : swr + 1;
    }
    // final: tile NT-1 (stage (NT-1)%4 == 3), owned by group ((NT-1)&1) == 1
    if (group == 1) {
        mma_stage(stg[3], acc, arow0, arow1, brow0, brow1, colb, swz);
        DRAIN();
    }

    // ---- combine groups into Cs (stage-0 region; final MMAs read stages 2/3)
    if (group == 0) {
#pragma unroll
        for (int im = 0; im < 2; im++)
#pragma unroll
            for (int n8 = 0; n8 < 4; n8++) {
                const int r0 = wm + im * 16 + (lid >> 2);
                const int c0 = wn + n8 * 8 + (lid & 3) * 2;
                *(float2*)&Cs[r0 * CRS + c0] = make_float2(sum[im][n8][0], sum[im][n8][1]);
                *(float2*)&Cs[(r0 + 8) * CRS + c0] = make_float2(sum[im][n8][2], sum[im][n8][3]);
            }
    }
    __syncthreads();
    if (group == 1) {
#pragma unroll
        for (int im = 0; im < 2; im++)
#pragma unroll
            for (int n8 = 0; n8 < 4; n8++) {
                const int r0 = wm + im * 16 + (lid >> 2);
                const int c0 = wn + n8 * 8 + (lid & 3) * 2;
                float2 a0 = *(float2*)&Cs[r0 * CRS + c0];
                float2 a1 = *(float2*)&Cs[(r0 + 8) * CRS + c0];
                *(float2*)&Cs[r0 * CRS + c0] =
                    make_float2(a0.x + sum[im][n8][0], a0.y + sum[im][n8][1]);
                *(float2*)&Cs[(r0 + 8) * CRS + c0] =
                    make_float2(a1.x + sum[im][n8][2], a1.y + sum[im][n8][3]);
            }
    }
    __syncthreads();

    if (tid < BM) {
        const int m  = tid;
        const int gm = block_m + m;
        float v[NEXP];
#pragma unroll
        for (int e = 0; e < NEXP; e++)
            v[e] = Cs[m * CRS + e] * SCALE_OUT + biasS[e];

        float* outR    = out;
        float* outWt   = out + (size_t)N_TOKENS * NEXP;
        float* outIdx  = outWt + (size_t)N_TOKENS * TOPK;
        float* outMask = outIdx + (size_t)N_TOKENS * TOPK;

        float* dst = outR + (size_t)gm * NEXP;
#pragma unroll
        for (int e = 0; e < NEXP; e += 4)
            *(float4*)(dst + e) = make_float4(v[e], v[e + 1], v[e + 2], v[e + 3]);

        // top-8, strict > (first index on ties, matching jax top_k)
        unsigned long long used = 0ull;
        float vals[TOPK]; int idxs[TOPK];
#pragma unroll
        for (int k = 0; k < TOPK; k++) {
            float best = -INFINITY; int bi = 0;
#pragma unroll
            for (int e = 0; e < NEXP; e++) {
                const bool free_e = !((used >> e) & 1ull);
                if (free_e && v[e] > best) { best = v[e]; bi = e; }
            }
            used |= 1ull << bi;
            vals[k] = best; idxs[k] = bi;
        }
        const float mx = vals[0];
        float ex[TOPK], s = 0.0f;
#pragma unroll
        for (int k = 0; k < TOPK; k++) { ex[k] = expf(vals[k] - mx); s += ex[k]; }
        const float inv = 1.0f / s;

        *(float4*)(outWt + (size_t)gm * TOPK) =
            make_float4(ex[0] * inv, ex[1] * inv, ex[2] * inv, ex[3] * inv);
        *(float4*)(outWt + (size_t)gm * TOPK + 4) =
            make_float4(ex[4] * inv, ex[5] * inv, ex[6] * inv, ex[7] * inv);
        *(float4*)(outIdx + (size_t)gm * TOPK) =
            make_float4((float)idxs[0], (float)idxs[1], (float)idxs[2], (float)idxs[3]);
        *(float4*)(outIdx + (size_t)gm * TOPK + 4) =
            make_float4((float)idxs[4], (float)idxs[5], (float)idxs[6], (float)idxs[7]);
#pragma unroll
        for (int k = 0; k < TOPK; k++)
            outMask[(size_t)(idxs[k] * TOPK + k) * N_TOKENS + gm] = 1.0f;
    }
}

extern "C" void kernel_launch(void* const* d_in, const int* in_sizes, int n_in,
                              void* d_out, int out_size)
{
    const float* x = (const float*)d_in[0];
    const float* W = (const float*)d_in[1];
    const float* b = (const float*)d_in[2];
    float* out = (float*)d_out;

    // zero the expert_mask region (rest of out fully overwritten)
    float* mask = out + (size_t)N_TOKENS * NEXP + 2 * (size_t)N_TOKENS * TOPK;
    cudaMemsetAsync(mask, 0, (size_t)NEXP * TOPK * N_TOKENS * sizeof(float), 0);

    wsplit_kernel<<<NT, 256>>>(W);

    cudaFuncSetAttribute(router_kernel,
                         cudaFuncAttributeMaxDynamicSharedMemorySize, SMEM_BYTES);
    router_kernel<<<N_TOKENS / BM, NTH, SMEM_BYTES>>>(x, b, out);
}